// round 15
// baseline (speedup 1.0000x reference)
#include <cuda_runtime.h>
#include <cuda_bf16.h>
#include <math.h>
#include <stdint.h>

#define NB 8
#define CD 128
#define KC 64
#define HD 16
#define WD 900
#define HW 14400
#define NCH 90
#define NW 30
#define NR 240
#define NRP 256
#define OD 256
#define KSP 32
#define KD 8192

__device__ float g_cwx[(size_t)NB * NCH * KC * CD];       // (n,j,k,c)
__device__ float g_ca[(size_t)NB * NCH * KC];             // (n,j,k)
__device__ unsigned short g_vh[(size_t)NRP * KD];         // vlad bf16 hi (rows>=240 stay 0)
__device__ unsigned short g_vl[(size_t)NRP * KD];
__device__ unsigned short g_wh[(size_t)OD * KD];
__device__ unsigned short g_wl[(size_t)OD * KD];
__device__ unsigned short g_cwh[KC * CD];                 // conv_w bf16 hi
__device__ unsigned short g_cwl[KC * CD];
__device__ float g_part[(size_t)KSP * NR * OD];

__device__ __forceinline__ uint32_t smem_u32(const void* p) {
    uint32_t a;
    asm("{ .reg .u64 t; cvta.to.shared.u64 t, %1; cvt.u32.u64 %0, t; }"
        : "=r"(a) : "l"(p));
    return a;
}
__device__ __forceinline__ void ldm_x4(uint32_t (&r)[4], uint32_t addr) {
    asm volatile("ldmatrix.sync.aligned.m8n8.x4.shared.b16 {%0,%1,%2,%3}, [%4];"
                 : "=r"(r[0]), "=r"(r[1]), "=r"(r[2]), "=r"(r[3]) : "r"(addr));
}
__device__ __forceinline__ void ldm_x4t(uint32_t (&r)[4], uint32_t addr) {
    asm volatile("ldmatrix.sync.aligned.m8n8.x4.trans.shared.b16 {%0,%1,%2,%3}, [%4];"
                 : "=r"(r[0]), "=r"(r[1]), "=r"(r[2]), "=r"(r[3]) : "r"(addr));
}
__device__ __forceinline__ void mma16816(float (&d)[4], const uint32_t (&a)[4],
                                         const uint32_t b0, const uint32_t b1) {
    asm volatile(
        "mma.sync.aligned.m16n8k16.row.col.f32.bf16.bf16.f32 "
        "{%0,%1,%2,%3}, {%4,%5,%6,%7}, {%8,%9}, {%0,%1,%2,%3};"
        : "+f"(d[0]), "+f"(d[1]), "+f"(d[2]), "+f"(d[3])
        : "r"(a[0]), "r"(a[1]), "r"(a[2]), "r"(a[3]), "r"(b0), "r"(b1));
}
__device__ __forceinline__ void bsplit2(float x0, float x1,
                                        uint32_t& h2, uint32_t& l2) {
    asm("cvt.rn.bf16x2.f32 %0, %1, %2;" : "=r"(h2) : "f"(x1), "f"(x0));
    float h0 = __uint_as_float(h2 << 16);
    float h1 = __uint_as_float(h2 & 0xffff0000u);
    float r0 = x0 - h0, r1 = x1 - h1;
    asm("cvt.rn.bf16x2.f32 %0, %1, %2;" : "=r"(l2) : "f"(r1), "f"(r0));
}
__device__ __forceinline__ void cpa16(uint32_t saddr, const void* g) {
    asm volatile("cp.async.cg.shared.global [%0], [%1], 16;" :: "r"(saddr), "l"(g));
}
#define CPA_COMMIT() asm volatile("cp.async.commit_group;" ::: "memory")
#define CPA_WAIT1()  asm volatile("cp.async.wait_group 1;" ::: "memory")
#define CPA_WAIT0()  asm volatile("cp.async.wait_group 0;" ::: "memory")

__global__ __launch_bounds__(256) void kW(const float* __restrict__ mw) {
    size_t base = ((size_t)blockIdx.x * 256 + threadIdx.x) * 8;
    float4 v0 = *(const float4*)(mw + base);
    float4 v1 = *(const float4*)(mw + base + 4);
    uint32_t h[4], l[4];
    bsplit2(v0.x, v0.y, h[0], l[0]);
    bsplit2(v0.z, v0.w, h[1], l[1]);
    bsplit2(v1.x, v1.y, h[2], l[2]);
    bsplit2(v1.z, v1.w, h[3], l[3]);
    *(uint4*)(g_wh + base) = make_uint4(h[0], h[1], h[2], h[3]);
    *(uint4*)(g_wl + base) = make_uint4(l[0], l[1], l[2], l[3]);
}

__global__ __launch_bounds__(256) void kWc(const float* __restrict__ cw) {
    int base = (blockIdx.x * 256 + threadIdx.x) * 4;
    float4 v = *(const float4*)(cw + base);
    uint32_t h[2], l[2];
    bsplit2(v.x, v.y, h[0], l[0]);
    bsplit2(v.z, v.w, h[1], l[1]);
    *(uint2*)(g_cwh + base) = make_uint2(h[0], h[1]);
    *(uint2*)(g_cwl + base) = make_uint2(l[0], l[1]);
}

#define F_RS   168
#define F_WRS  136
#define F_WH   0
#define F_WL   17408
#define F_XH   34816
#define F_XL   77824
#define F_AH   120832
#define F_AL   142336
#define F_CB   163840
#define F_CA   164096
#define F_SMEM 164352

__global__ __launch_bounds__(320, 1) void kF(const float* __restrict__ x,
                                             const float* __restrict__ cb) {
    extern __shared__ char smem[];
    const uint32_t sb = smem_u32(smem);
    unsigned short* sWH = (unsigned short*)(smem + F_WH);
    unsigned short* sWL = (unsigned short*)(smem + F_WL);
    unsigned short* sXH = (unsigned short*)(smem + F_XH);
    unsigned short* sXL = (unsigned short*)(smem + F_XL);
    unsigned short* sAH = (unsigned short*)(smem + F_AH);
    unsigned short* sAL = (unsigned short*)(smem + F_AL);
    float* cbs = (float*)(smem + F_CB);
    float* sCA = (float*)(smem + F_CA);

    const int tid = threadIdx.x;
    const int wid = tid >> 5;
    const int L   = tid & 31;
    const int n = blockIdx.x / NCH;
    const int j = blockIdx.x % NCH;

    const int a_row = (L & 7) + ((L >> 3) & 1) * 8;
    const int a_ch  = (L >> 4) * 8;
    const int b_row = (L & 7) + (L >> 4) * 8;
    const int b_ch  = ((L >> 3) & 1) * 8;

    for (int idx = tid; idx < 1024; idx += 320) {
        int k = idx >> 4, seg = (idx & 15) * 8;
        *(uint4*)&sWH[k * F_WRS + seg] = *(const uint4*)&g_cwh[k * CD + seg];
        *(uint4*)&sWL[k * F_WRS + seg] = *(const uint4*)&g_cwl[k * CD + seg];
    }
    if (tid < 64) cbs[tid] = cb[tid];
    if (tid >= 64 && tid < 128) sCA[tid - 64] = 0.f;

    // x-staging: 10240 float2; 5 lanes share one (c,h) 40B row span.
    // 320 = 64*5 -> row = tid/5 + it*64, w2 = tid%5 (div hoisted out of loop)
    {
        const float* xb = x + (size_t)n * CD * HW + (size_t)j * 10;
        const int r00 = tid / 5;
        const int w2  = tid - r00 * 5;
#pragma unroll 8
        for (int it = 0; it < 32; ++it) {
            int row = r00 + it * 64;
            int c = row >> 4, h = row & 15;
            float2 v = *(const float2*)(xb + (size_t)c * HW + (size_t)h * WD + w2 * 2);
            uint32_t h2, l2;
            bsplit2(v.x, v.y, h2, l2);
            int colb = c * F_RS + h * 10 + w2 * 2;
            *(uint*)&sXH[colb] = h2;
            *(uint*)&sXL[colb] = l2;
        }
    }
    __syncthreads();

    const int qt = wid * 16;
    float lg[4][2][4];
#pragma unroll
    for (int mi = 0; mi < 4; mi++)
#pragma unroll
        for (int ni = 0; ni < 2; ni++)
#pragma unroll
            for (int e = 0; e < 4; e++) lg[mi][ni][e] = 0.f;

#pragma unroll
    for (int kc = 0; kc < 8; ++kc) {
        uint32_t bxh[4], bxl[4];
        uint32_t offx = (uint32_t)((kc * 16 + a_row) * F_RS + qt + a_ch) * 2;
        ldm_x4t(bxh, sb + F_XH + offx);
        ldm_x4t(bxl, sb + F_XL + offx);
#pragma unroll
        for (int mi = 0; mi < 4; ++mi) {
            uint32_t wh[4], wl[4];
            uint32_t offw = (uint32_t)((mi * 16 + a_row) * F_WRS + kc * 16 + a_ch) * 2;
            ldm_x4(wh, sb + F_WH + offw);
            ldm_x4(wl, sb + F_WL + offw);
#pragma unroll
            for (int ni = 0; ni < 2; ++ni) {
                uint32_t b0h = bxh[ni * 2], b1h = bxh[ni * 2 + 1];
                uint32_t b0l = bxl[ni * 2], b1l = bxl[ni * 2 + 1];
                mma16816(lg[mi][ni], wh, b0h, b1h);
                mma16816(lg[mi][ni], wh, b0l, b1l);
                mma16816(lg[mi][ni], wl, b0h, b1h);
            }
        }
    }

    const int r0 = L >> 2;
#pragma unroll
    for (int mi = 0; mi < 4; ++mi) {
        float b0 = cbs[mi * 16 + r0];
        float b1 = cbs[mi * 16 + r0 + 8];
#pragma unroll
        for (int ni = 0; ni < 2; ++ni) {
            lg[mi][ni][0] += b0; lg[mi][ni][1] += b0;
            lg[mi][ni][2] += b1; lg[mi][ni][3] += b1;
        }
    }

    float mx[4];
#pragma unroll
    for (int ni = 0; ni < 2; ++ni)
#pragma unroll
        for (int h = 0; h < 2; ++h) {
            float m = -1e30f;
#pragma unroll
            for (int mi = 0; mi < 4; ++mi)
                m = fmaxf(m, fmaxf(lg[mi][ni][h], lg[mi][ni][2 + h]));
            mx[ni * 2 + h] = m;
        }
#pragma unroll
    for (int e = 0; e < 4; ++e) {
        mx[e] = fmaxf(mx[e], __shfl_xor_sync(0xffffffffu, mx[e], 4));
        mx[e] = fmaxf(mx[e], __shfl_xor_sync(0xffffffffu, mx[e], 8));
        mx[e] = fmaxf(mx[e], __shfl_xor_sync(0xffffffffu, mx[e], 16));
    }
    float sm[4] = {0.f, 0.f, 0.f, 0.f};
#pragma unroll
    for (int mi = 0; mi < 4; ++mi)
#pragma unroll
        for (int ni = 0; ni < 2; ++ni)
#pragma unroll
            for (int e = 0; e < 4; ++e) {
                lg[mi][ni][e] = __expf(lg[mi][ni][e] - mx[ni * 2 + (e & 1)]);
                sm[ni * 2 + (e & 1)] += lg[mi][ni][e];
            }
#pragma unroll
    for (int e = 0; e < 4; ++e) {
        sm[e] += __shfl_xor_sync(0xffffffffu, sm[e], 4);
        sm[e] += __shfl_xor_sync(0xffffffffu, sm[e], 8);
        sm[e] += __shfl_xor_sync(0xffffffffu, sm[e], 16);
        sm[e] = 1.0f / sm[e];
    }
#pragma unroll
    for (int mi = 0; mi < 4; ++mi)
#pragma unroll
        for (int ni = 0; ni < 2; ++ni)
#pragma unroll
            for (int e = 0; e < 4; ++e)
                lg[mi][ni][e] *= sm[ni * 2 + (e & 1)];

#pragma unroll
    for (int mi = 0; mi < 4; ++mi)
#pragma unroll
        for (int rh = 0; rh < 2; ++rh) {
            float rs = lg[mi][0][rh * 2] + lg[mi][0][rh * 2 + 1] +
                       lg[mi][1][rh * 2] + lg[mi][1][rh * 2 + 1];
            rs += __shfl_xor_sync(0xffffffffu, rs, 1);
            rs += __shfl_xor_sync(0xffffffffu, rs, 2);
            if ((L & 3) == 0)
                atomicAdd(&sCA[mi * 16 + r0 + rh * 8], rs);
        }

    {
        int qb = qt + (L & 3) * 2;
#pragma unroll
        for (int mi = 0; mi < 4; ++mi)
#pragma unroll
            for (int ni = 0; ni < 2; ++ni)
#pragma unroll
                for (int rh = 0; rh < 2; ++rh) {
                    int k = mi * 16 + r0 + rh * 8;
                    int q0 = qb + ni * 8;
                    uint32_t h2, l2;
                    bsplit2(lg[mi][ni][rh * 2], lg[mi][ni][rh * 2 + 1], h2, l2);
                    *(uint*)&sAH[k * F_RS + q0] = h2;
                    *(uint*)&sAL[k * F_RS + q0] = l2;
                }
    }
    __syncthreads();

    if (tid < 64)
        g_ca[((size_t)n * NCH + j) * KC + tid] = sCA[tid];

    if (wid < 8) {
        const int wk = wid & 3;
        const int wc = wid >> 2;
        float acc[8][4];
#pragma unroll
        for (int ni = 0; ni < 8; ni++)
#pragma unroll
            for (int e = 0; e < 4; e++) acc[ni][e] = 0.f;

#pragma unroll
        for (int kq = 0; kq < 10; ++kq) {
            int kc = kq * 16;
            uint32_t ah[4], al[4];
            uint32_t offa = (uint32_t)((wk * 16 + a_row) * F_RS + kc + a_ch) * 2;
            ldm_x4(ah, sb + F_AH + offa);
            ldm_x4(al, sb + F_AL + offa);
            uint32_t bh[4][4], bl[4][4];
#pragma unroll
            for (int nb = 0; nb < 4; ++nb) {
                uint32_t offb = (uint32_t)((wc * 64 + nb * 16 + b_row) * F_RS + kc + b_ch) * 2;
                ldm_x4(bh[nb], sb + F_XH + offb);
                ldm_x4(bl[nb], sb + F_XL + offb);
            }
#pragma unroll
            for (int ni = 0; ni < 8; ++ni) {
                uint32_t b0h = bh[ni >> 1][(ni & 1) * 2];
                uint32_t b1h = bh[ni >> 1][(ni & 1) * 2 + 1];
                uint32_t b0l = bl[ni >> 1][(ni & 1) * 2];
                uint32_t b1l = bl[ni >> 1][(ni & 1) * 2 + 1];
                mma16816(acc[ni], ah, b0h, b1h);
                mma16816(acc[ni], ah, b0l, b1l);
                mma16816(acc[ni], al, b0h, b1h);
            }
        }

        float* ob = g_cwx + (size_t)(n * NCH + j) * KC * CD;
        int k0  = wk * 16 + (L >> 2);
        int cb0 = wc * 64 + (L & 3) * 2;
#pragma unroll
        for (int ni = 0; ni < 8; ++ni) {
            int c = cb0 + ni * 8;
            *(float2*)&ob[(size_t)k0 * CD + c]       = make_float2(acc[ni][0], acc[ni][1]);
            *(float2*)&ob[(size_t)(k0 + 8) * CD + c] = make_float2(acc[ni][2], acc[ni][3]);
        }
    }
}

#define TG 6
#define TW 5

__global__ __launch_bounds__(256) void kC1(const float* __restrict__ centers) {
    const int wi = blockIdx.x * 8 + (threadIdx.x >> 5);
    const int L  = threadIdx.x & 31;
    const int g  = wi % TG;
    const int k  = (wi / TG) & 63;
    const int n  = wi / (TG * KC);
    const int c4 = L * 4;

    const float* cwb = g_cwx + ((size_t)n * NCH * KC + k) * CD + c4;
    const float* cab = g_ca + (size_t)n * NCH * KC + k;
    const size_t cstep = (size_t)KC * CD;

    const int t0 = g * TW;
    float s0 = 0.f, s1 = 0.f, s2 = 0.f, s3 = 0.f, As = 0.f;
#pragma unroll
    for (int i = 0; i < 20; ++i) {
        int jj = 3 * t0 + i + 80;
        if (jj >= NCH) jj -= NCH;
        if (jj >= NCH) jj -= NCH;
        float4 v = *(const float4*)(cwb + (size_t)jj * cstep);
        s0 += v.x; s1 += v.y; s2 += v.z; s3 += v.w;
        As += cab[(size_t)jj * KC];
    }
    const float4 cen = *(const float4*)&centers[(size_t)k * CD + c4];

#pragma unroll
    for (int t = t0; t < t0 + TW; ++t) {
        float r0 = s0 - cen.x * As;
        float r1 = s1 - cen.y * As;
        float r2 = s2 - cen.z * As;
        float r3 = s3 - cen.w * As;
        float ns = r0 * r0 + r1 * r1 + r2 * r2 + r3 * r3;
#pragma unroll
        for (int off = 16; off > 0; off >>= 1)
            ns += __shfl_xor_sync(0xffffffffu, ns, off);
        float inv = 0.125f / fmaxf(sqrtf(ns), 1e-12f);

        uint32_t h01, l01, h23, l23;
        bsplit2(r0 * inv, r1 * inv, h01, l01);
        bsplit2(r2 * inv, r3 * inv, h23, l23);
        size_t idx = (size_t)(n * NW + t) * KD + (size_t)k * CD + c4;
        *(uint2*)&g_vh[idx] = make_uint2(h01, h23);
        *(uint2*)&g_vl[idx] = make_uint2(l01, l23);

        if (t < t0 + TW - 1) {
#pragma unroll
            for (int d = 0; d < 3; ++d) {
                int ja = 3 * t + 10 + d;
                if (ja >= NCH) ja -= NCH;
                int js = 3 * t + 80 + d;
                if (js >= NCH) js -= NCH;
                if (js >= NCH) js -= NCH;
                float4 va = *(const float4*)(cwb + (size_t)ja * cstep);
                float4 vs = *(const float4*)(cwb + (size_t)js * cstep);
                s0 += va.x - vs.x; s1 += va.y - vs.y;
                s2 += va.z - vs.z; s3 += va.w - vs.w;
                As += cab[(size_t)ja * KC] - cab[(size_t)js * KC];
            }
        }
    }
}

// ---------------------------------------------------------------------------
// Kernel C2 v3: BM=64, BN=64, warp tile m16 x n32, grid (4,4,32).
// 73.7 KB smem double-buffered -> 2 CTAs/SM. K-chunk 256 (4 stages of 64).
// ---------------------------------------------------------------------------
#define C2_RS   72
#define C2_AH   0
#define C2_AL   9216
#define C2_BH   18432
#define C2_BL   27648
#define C2_BUF  36864
#define C2_SMEM (C2_BUF * 2)

__device__ __forceinline__ void c2_stage(uint32_t sbuf, int m0, int n0, int kb,
                                         int tid) {
#pragma unroll
    for (int it = 0; it < 2; ++it) {
        int p = tid + it * 256;
        int row = p >> 3, cg = (p & 7) * 8;
        size_t g = (size_t)(m0 + row) * KD + kb + cg;
        cpa16(sbuf + C2_AH + (row * C2_RS + cg) * 2, &g_vh[g]);
        cpa16(sbuf + C2_AL + (row * C2_RS + cg) * 2, &g_vl[g]);
    }
#pragma unroll
    for (int it = 0; it < 2; ++it) {
        int p = tid + it * 256;
        int row = p >> 3, cg = (p & 7) * 8;
        size_t g = (size_t)(n0 + row) * KD + kb + cg;
        cpa16(sbuf + C2_BH + (row * C2_RS + cg) * 2, &g_wh[g]);
        cpa16(sbuf + C2_BL + (row * C2_RS + cg) * 2, &g_wl[g]);
    }
}

__global__ __launch_bounds__(256, 2) void kC2() {
    extern __shared__ char smem[];
    const uint32_t sb = smem_u32(smem);
    const int tid = threadIdx.x;
    const int wid = tid >> 5;
    const int L   = tid & 31;
    const int m0  = blockIdx.x * 64;
    const int n0  = blockIdx.y * 64;
    const int k0  = blockIdx.z * 256;

    const int wm = wid & 3;    // m tile of 16
    const int wn = wid >> 2;   // n tile of 32

    float acc[4][4];
#pragma unroll
    for (int ni = 0; ni < 4; ni++)
#pragma unroll
        for (int e = 0; e < 4; e++) acc[ni][e] = 0.f;

    const int a_row = (L & 7) + ((L >> 3) & 1) * 8;
    const int a_ch  = (L >> 4) * 8;
    const int b_row = (L & 7) + (L >> 4) * 8;
    const int b_ch  = ((L >> 3) & 1) * 8;

    c2_stage(sb, m0, n0, k0, tid);
    CPA_COMMIT();

#pragma unroll
    for (int stage = 0; stage < 4; ++stage) {
        if (stage < 3) {
            c2_stage(sb + ((stage + 1) & 1) * C2_BUF, m0, n0, k0 + (stage + 1) * 64, tid);
            CPA_COMMIT();
            CPA_WAIT1();
        } else {
            CPA_WAIT0();
        }
        __syncthreads();
        uint32_t bufb = sb + (stage & 1) * C2_BUF;

#pragma unroll
        for (int ks = 0; ks < 4; ++ks) {
            int kc = ks * 16;
            uint32_t ah[4], al[4];
            {
                uint32_t off = (uint32_t)((wm * 16 + a_row) * C2_RS + kc + a_ch) * 2;
                ldm_x4(ah, bufb + C2_AH + off);
                ldm_x4(al, bufb + C2_AL + off);
            }
            uint32_t bh[2][4], bl[2][4];
#pragma unroll
            for (int nb = 0; nb < 2; ++nb) {
                uint32_t off = (uint32_t)((wn * 32 + nb * 16 + b_row) * C2_RS + kc + b_ch) * 2;
                ldm_x4(bh[nb], bufb + C2_BH + off);
                ldm_x4(bl[nb], bufb + C2_BL + off);
            }
#pragma unroll
            for (int ni = 0; ni < 4; ++ni) {
                uint32_t b0h = bh[ni >> 1][(ni & 1) * 2];
                uint32_t b1h = bh[ni >> 1][(ni & 1) * 2 + 1];
                uint32_t b0l = bl[ni >> 1][(ni & 1) * 2];
                uint32_t b1l = bl[ni >> 1][(ni & 1) * 2 + 1];
                mma16816(acc[ni], ah, b0h, b1h);
                mma16816(acc[ni], ah, b0l, b1l);
                mma16816(acc[ni], al, b0h, b1h);
            }
        }
        __syncthreads();
    }

    float* pb = g_part + (size_t)blockIdx.z * NR * OD;
    int m_lo = m0 + wm * 16 + (L >> 2);
    int nn   = n0 + wn * 32 + (L & 3) * 2;
#pragma unroll
    for (int ni = 0; ni < 4; ++ni) {
        int nc = nn + ni * 8;
        if (m_lo < NR)
            *(float2*)&pb[(size_t)m_lo * OD + nc] =
                make_float2(acc[ni][0], acc[ni][1]);
        if (m_lo + 8 < NR)
            *(float2*)&pb[(size_t)(m_lo + 8) * OD + nc] =
                make_float2(acc[ni][2], acc[ni][3]);
    }
}

__global__ __launch_bounds__(256) void kC3(const float* __restrict__ mb,
                                           float* __restrict__ out) {
    __shared__ float red[8];
    const int rrow = blockIdx.x;
    const int tid  = threadIdx.x;
    float s = mb[tid];
#pragma unroll
    for (int ks = 0; ks < KSP; ks++)
        s += g_part[((size_t)ks * NR + rrow) * OD + tid];
    float sq = s * s;
#pragma unroll
    for (int off = 16; off > 0; off >>= 1)
        sq += __shfl_xor_sync(0xffffffffu, sq, off);
    if ((tid & 31) == 0) red[tid >> 5] = sq;
    __syncthreads();
    float tot = 0.f;
#pragma unroll
    for (int i = 0; i < 8; i++) tot += red[i];
    out[(size_t)rrow * OD + tid] = s / fmaxf(sqrtf(tot), 1e-12f);
}

extern "C" void kernel_launch(void* const* d_in, const int* in_sizes, int n_in,
                              void* d_out, int out_size) {
    (void)in_sizes; (void)n_in; (void)out_size;
    const float* x       = (const float*)d_in[0];
    const float* centers = (const float*)d_in[1];
    const float* cw      = (const float*)d_in[2];
    const float* cb      = (const float*)d_in[3];
    const float* mw      = (const float*)d_in[4];
    const float* mb      = (const float*)d_in[5];
    float* out = (float*)d_out;

    static cudaStream_t s2 = nullptr;
    static cudaEvent_t evFork = nullptr, evJoin = nullptr;
    if (!s2) {
        cudaStreamCreateWithFlags(&s2, cudaStreamNonBlocking);
        cudaEventCreateWithFlags(&evFork, cudaEventDisableTiming);
        cudaEventCreateWithFlags(&evJoin, cudaEventDisableTiming);
        cudaFuncSetAttribute(kF, cudaFuncAttributeMaxDynamicSharedMemorySize, F_SMEM);
        cudaFuncSetAttribute(kC2, cudaFuncAttributeMaxDynamicSharedMemorySize, C2_SMEM);
    }

    kWc<<<KC * CD / (256 * 4), 256>>>(cw);

    cudaEventRecord(evFork, 0);
    cudaStreamWaitEvent(s2, evFork, 0);
    kW<<<OD * KD / (256 * 8), 256, 0, s2>>>(mw);
    cudaEventRecord(evJoin, s2);

    kF<<<NB * NCH, 320, F_SMEM>>>(x, cb);
    kC1<<<NB * KC * TG / 8, 256>>>(centers);
    cudaStreamWaitEvent(0, evJoin, 0);
    kC2<<<dim3(4, 4, KSP), 256, C2_SMEM>>>();
    kC3<<<NR, 256>>>(mb, out);
}

// round 16
// speedup vs baseline: 1.0142x; 1.0142x over previous
#include <cuda_runtime.h>
#include <cuda_bf16.h>
#include <math.h>
#include <stdint.h>

#define NB 8
#define CD 128
#define KC 64
#define HD 16
#define WD 900
#define HW 14400
#define NCH 90
#define NW 30
#define NR 240
#define NRP 256
#define OD 256
#define KSP 32
#define KD 8192

__device__ float g_cwx[(size_t)NB * NCH * KC * CD];       // (n,j,k,c)
__device__ float g_ca[(size_t)NB * NCH * KC];             // (n,j,k)
__device__ unsigned short g_vh[(size_t)NRP * KD];         // vlad bf16 hi (rows>=240 stay 0)
__device__ unsigned short g_vl[(size_t)NRP * KD];
__device__ unsigned short g_wh[(size_t)OD * KD];
__device__ unsigned short g_wl[(size_t)OD * KD];
__device__ unsigned short g_cwh[KC * CD];                 // conv_w bf16 hi
__device__ unsigned short g_cwl[KC * CD];
__device__ float g_part[(size_t)KSP * NR * OD];

__device__ __forceinline__ uint32_t smem_u32(const void* p) {
    uint32_t a;
    asm("{ .reg .u64 t; cvta.to.shared.u64 t, %1; cvt.u32.u64 %0, t; }"
        : "=r"(a) : "l"(p));
    return a;
}
__device__ __forceinline__ void ldm_x4(uint32_t (&r)[4], uint32_t addr) {
    asm volatile("ldmatrix.sync.aligned.m8n8.x4.shared.b16 {%0,%1,%2,%3}, [%4];"
                 : "=r"(r[0]), "=r"(r[1]), "=r"(r[2]), "=r"(r[3]) : "r"(addr));
}
__device__ __forceinline__ void ldm_x4t(uint32_t (&r)[4], uint32_t addr) {
    asm volatile("ldmatrix.sync.aligned.m8n8.x4.trans.shared.b16 {%0,%1,%2,%3}, [%4];"
                 : "=r"(r[0]), "=r"(r[1]), "=r"(r[2]), "=r"(r[3]) : "r"(addr));
}
__device__ __forceinline__ void mma16816(float (&d)[4], const uint32_t (&a)[4],
                                         const uint32_t b0, const uint32_t b1) {
    asm volatile(
        "mma.sync.aligned.m16n8k16.row.col.f32.bf16.bf16.f32 "
        "{%0,%1,%2,%3}, {%4,%5,%6,%7}, {%8,%9}, {%0,%1,%2,%3};"
        : "+f"(d[0]), "+f"(d[1]), "+f"(d[2]), "+f"(d[3])
        : "r"(a[0]), "r"(a[1]), "r"(a[2]), "r"(a[3]), "r"(b0), "r"(b1));
}
__device__ __forceinline__ void bsplit2(float x0, float x1,
                                        uint32_t& h2, uint32_t& l2) {
    asm("cvt.rn.bf16x2.f32 %0, %1, %2;" : "=r"(h2) : "f"(x1), "f"(x0));
    float h0 = __uint_as_float(h2 << 16);
    float h1 = __uint_as_float(h2 & 0xffff0000u);
    float r0 = x0 - h0, r1 = x1 - h1;
    asm("cvt.rn.bf16x2.f32 %0, %1, %2;" : "=r"(l2) : "f"(r1), "f"(r0));
}
__device__ __forceinline__ void cpa16(uint32_t saddr, const void* g) {
    asm volatile("cp.async.cg.shared.global [%0], [%1], 16;" :: "r"(saddr), "l"(g));
}
#define CPA_COMMIT() asm volatile("cp.async.commit_group;" ::: "memory")
#define CPA_WAIT1()  asm volatile("cp.async.wait_group 1;" ::: "memory")
#define CPA_WAIT0()  asm volatile("cp.async.wait_group 0;" ::: "memory")

__global__ __launch_bounds__(256) void kW(const float* __restrict__ mw) {
    size_t base = ((size_t)blockIdx.x * 256 + threadIdx.x) * 8;
    float4 v0 = *(const float4*)(mw + base);
    float4 v1 = *(const float4*)(mw + base + 4);
    uint32_t h[4], l[4];
    bsplit2(v0.x, v0.y, h[0], l[0]);
    bsplit2(v0.z, v0.w, h[1], l[1]);
    bsplit2(v1.x, v1.y, h[2], l[2]);
    bsplit2(v1.z, v1.w, h[3], l[3]);
    *(uint4*)(g_wh + base) = make_uint4(h[0], h[1], h[2], h[3]);
    *(uint4*)(g_wl + base) = make_uint4(l[0], l[1], l[2], l[3]);
}

__global__ __launch_bounds__(256) void kWc(const float* __restrict__ cw) {
    int base = (blockIdx.x * 256 + threadIdx.x) * 4;
    float4 v = *(const float4*)(cw + base);
    uint32_t h[2], l[2];
    bsplit2(v.x, v.y, h[0], l[0]);
    bsplit2(v.z, v.w, h[1], l[1]);
    *(uint2*)(g_cwh + base) = make_uint2(h[0], h[1]);
    *(uint2*)(g_cwl + base) = make_uint2(l[0], l[1]);
}

#define F_RS   168
#define F_WRS  136
#define F_WH   0
#define F_WL   17408
#define F_XH   34816
#define F_XL   77824
#define F_AH   120832
#define F_AL   142336
#define F_CB   163840
#define F_CA   164096
#define F_SMEM 164352

__global__ __launch_bounds__(320, 1) void kF(const float* __restrict__ x,
                                             const float* __restrict__ cb) {
    extern __shared__ char smem[];
    const uint32_t sb = smem_u32(smem);
    unsigned short* sWH = (unsigned short*)(smem + F_WH);
    unsigned short* sWL = (unsigned short*)(smem + F_WL);
    unsigned short* sXH = (unsigned short*)(smem + F_XH);
    unsigned short* sXL = (unsigned short*)(smem + F_XL);
    unsigned short* sAH = (unsigned short*)(smem + F_AH);
    unsigned short* sAL = (unsigned short*)(smem + F_AL);
    float* cbs = (float*)(smem + F_CB);
    float* sCA = (float*)(smem + F_CA);

    const int tid = threadIdx.x;
    const int wid = tid >> 5;
    const int L   = tid & 31;
    const int n = blockIdx.x / NCH;
    const int j = blockIdx.x % NCH;

    const int a_row = (L & 7) + ((L >> 3) & 1) * 8;
    const int a_ch  = (L >> 4) * 8;
    const int b_row = (L & 7) + (L >> 4) * 8;
    const int b_ch  = ((L >> 3) & 1) * 8;

    for (int idx = tid; idx < 1024; idx += 320) {
        int k = idx >> 4, seg = (idx & 15) * 8;
        *(uint4*)&sWH[k * F_WRS + seg] = *(const uint4*)&g_cwh[k * CD + seg];
        *(uint4*)&sWL[k * F_WRS + seg] = *(const uint4*)&g_cwl[k * CD + seg];
    }
    if (tid < 64) cbs[tid] = cb[tid];
    if (tid >= 64 && tid < 128) sCA[tid - 64] = 0.f;

    // x-staging: 10240 float2; 5 lanes share one (c,h) 40B row span.
    {
        const float* xb = x + (size_t)n * CD * HW + (size_t)j * 10;
        const int r00 = tid / 5;
        const int w2  = tid - r00 * 5;
#pragma unroll 8
        for (int it = 0; it < 32; ++it) {
            int row = r00 + it * 64;
            int c = row >> 4, h = row & 15;
            float2 v = *(const float2*)(xb + (size_t)c * HW + (size_t)h * WD + w2 * 2);
            uint32_t h2, l2;
            bsplit2(v.x, v.y, h2, l2);
            int colb = c * F_RS + h * 10 + w2 * 2;
            *(uint*)&sXH[colb] = h2;
            *(uint*)&sXL[colb] = l2;
        }
    }
    __syncthreads();

    const int qt = wid * 16;
    float lg[4][2][4];
#pragma unroll
    for (int mi = 0; mi < 4; mi++)
#pragma unroll
        for (int ni = 0; ni < 2; ni++)
#pragma unroll
            for (int e = 0; e < 4; e++) lg[mi][ni][e] = 0.f;

#pragma unroll
    for (int kc = 0; kc < 8; ++kc) {
        uint32_t bxh[4], bxl[4];
        uint32_t offx = (uint32_t)((kc * 16 + a_row) * F_RS + qt + a_ch) * 2;
        ldm_x4t(bxh, sb + F_XH + offx);
        ldm_x4t(bxl, sb + F_XL + offx);
#pragma unroll
        for (int mi = 0; mi < 4; ++mi) {
            uint32_t wh[4], wl[4];
            uint32_t offw = (uint32_t)((mi * 16 + a_row) * F_WRS + kc * 16 + a_ch) * 2;
            ldm_x4(wh, sb + F_WH + offw);
            ldm_x4(wl, sb + F_WL + offw);
#pragma unroll
            for (int ni = 0; ni < 2; ++ni) {
                uint32_t b0h = bxh[ni * 2], b1h = bxh[ni * 2 + 1];
                uint32_t b0l = bxl[ni * 2], b1l = bxl[ni * 2 + 1];
                mma16816(lg[mi][ni], wh, b0h, b1h);
                mma16816(lg[mi][ni], wh, b0l, b1l);
                mma16816(lg[mi][ni], wl, b0h, b1h);
            }
        }
    }

    const int r0 = L >> 2;
#pragma unroll
    for (int mi = 0; mi < 4; ++mi) {
        float b0 = cbs[mi * 16 + r0];
        float b1 = cbs[mi * 16 + r0 + 8];
#pragma unroll
        for (int ni = 0; ni < 2; ++ni) {
            lg[mi][ni][0] += b0; lg[mi][ni][1] += b0;
            lg[mi][ni][2] += b1; lg[mi][ni][3] += b1;
        }
    }

    float mx[4];
#pragma unroll
    for (int ni = 0; ni < 2; ++ni)
#pragma unroll
        for (int h = 0; h < 2; ++h) {
            float m = -1e30f;
#pragma unroll
            for (int mi = 0; mi < 4; ++mi)
                m = fmaxf(m, fmaxf(lg[mi][ni][h], lg[mi][ni][2 + h]));
            mx[ni * 2 + h] = m;
        }
#pragma unroll
    for (int e = 0; e < 4; ++e) {
        mx[e] = fmaxf(mx[e], __shfl_xor_sync(0xffffffffu, mx[e], 4));
        mx[e] = fmaxf(mx[e], __shfl_xor_sync(0xffffffffu, mx[e], 8));
        mx[e] = fmaxf(mx[e], __shfl_xor_sync(0xffffffffu, mx[e], 16));
    }
    float sm[4] = {0.f, 0.f, 0.f, 0.f};
#pragma unroll
    for (int mi = 0; mi < 4; ++mi)
#pragma unroll
        for (int ni = 0; ni < 2; ++ni)
#pragma unroll
            for (int e = 0; e < 4; ++e) {
                lg[mi][ni][e] = __expf(lg[mi][ni][e] - mx[ni * 2 + (e & 1)]);
                sm[ni * 2 + (e & 1)] += lg[mi][ni][e];
            }
#pragma unroll
    for (int e = 0; e < 4; ++e) {
        sm[e] += __shfl_xor_sync(0xffffffffu, sm[e], 4);
        sm[e] += __shfl_xor_sync(0xffffffffu, sm[e], 8);
        sm[e] += __shfl_xor_sync(0xffffffffu, sm[e], 16);
        sm[e] = 1.0f / sm[e];
    }
#pragma unroll
    for (int mi = 0; mi < 4; ++mi)
#pragma unroll
        for (int ni = 0; ni < 2; ++ni)
#pragma unroll
            for (int e = 0; e < 4; ++e)
                lg[mi][ni][e] *= sm[ni * 2 + (e & 1)];

#pragma unroll
    for (int mi = 0; mi < 4; ++mi)
#pragma unroll
        for (int rh = 0; rh < 2; ++rh) {
            float rs = lg[mi][0][rh * 2] + lg[mi][0][rh * 2 + 1] +
                       lg[mi][1][rh * 2] + lg[mi][1][rh * 2 + 1];
            rs += __shfl_xor_sync(0xffffffffu, rs, 1);
            rs += __shfl_xor_sync(0xffffffffu, rs, 2);
            if ((L & 3) == 0)
                atomicAdd(&sCA[mi * 16 + r0 + rh * 8], rs);
        }

    {
        int qb = qt + (L & 3) * 2;
#pragma unroll
        for (int mi = 0; mi < 4; ++mi)
#pragma unroll
            for (int ni = 0; ni < 2; ++ni)
#pragma unroll
                for (int rh = 0; rh < 2; ++rh) {
                    int k = mi * 16 + r0 + rh * 8;
                    int q0 = qb + ni * 8;
                    uint32_t h2, l2;
                    bsplit2(lg[mi][ni][rh * 2], lg[mi][ni][rh * 2 + 1], h2, l2);
                    *(uint*)&sAH[k * F_RS + q0] = h2;
                    *(uint*)&sAL[k * F_RS + q0] = l2;
                }
    }
    __syncthreads();

    if (tid < 64)
        g_ca[((size_t)n * NCH + j) * KC + tid] = sCA[tid];

    if (wid < 8) {
        const int wk = wid & 3;
        const int wc = wid >> 2;
        float acc[8][4];
#pragma unroll
        for (int ni = 0; ni < 8; ni++)
#pragma unroll
            for (int e = 0; e < 4; e++) acc[ni][e] = 0.f;

#pragma unroll
        for (int kq = 0; kq < 10; ++kq) {
            int kc = kq * 16;
            uint32_t ah[4], al[4];
            uint32_t offa = (uint32_t)((wk * 16 + a_row) * F_RS + kc + a_ch) * 2;
            ldm_x4(ah, sb + F_AH + offa);
            ldm_x4(al, sb + F_AL + offa);
            uint32_t bh[4][4], bl[4][4];
#pragma unroll
            for (int nb = 0; nb < 4; ++nb) {
                uint32_t offb = (uint32_t)((wc * 64 + nb * 16 + b_row) * F_RS + kc + b_ch) * 2;
                ldm_x4(bh[nb], sb + F_XH + offb);
                ldm_x4(bl[nb], sb + F_XL + offb);
            }
#pragma unroll
            for (int ni = 0; ni < 8; ++ni) {
                uint32_t b0h = bh[ni >> 1][(ni & 1) * 2];
                uint32_t b1h = bh[ni >> 1][(ni & 1) * 2 + 1];
                uint32_t b0l = bl[ni >> 1][(ni & 1) * 2];
                uint32_t b1l = bl[ni >> 1][(ni & 1) * 2 + 1];
                mma16816(acc[ni], ah, b0h, b1h);
                mma16816(acc[ni], ah, b0l, b1l);
                mma16816(acc[ni], al, b0h, b1h);
            }
        }

        float* ob = g_cwx + (size_t)(n * NCH + j) * KC * CD;
        int k0  = wk * 16 + (L >> 2);
        int cb0 = wc * 64 + (L & 3) * 2;
#pragma unroll
        for (int ni = 0; ni < 8; ++ni) {
            int c = cb0 + ni * 8;
            *(float2*)&ob[(size_t)k0 * CD + c]       = make_float2(acc[ni][0], acc[ni][1]);
            *(float2*)&ob[(size_t)(k0 + 8) * CD + c] = make_float2(acc[ni][2], acc[ni][3]);
        }
    }
}

#define TG 6
#define TW 5

__global__ __launch_bounds__(256) void kC1(const float* __restrict__ centers) {
    const int wi = blockIdx.x * 8 + (threadIdx.x >> 5);
    const int L  = threadIdx.x & 31;
    const int g  = wi % TG;
    const int k  = (wi / TG) & 63;
    const int n  = wi / (TG * KC);
    const int c4 = L * 4;

    const float* cwb = g_cwx + ((size_t)n * NCH * KC + k) * CD + c4;
    const float* cab = g_ca + (size_t)n * NCH * KC + k;
    const size_t cstep = (size_t)KC * CD;

    const int t0 = g * TW;
    float s0 = 0.f, s1 = 0.f, s2 = 0.f, s3 = 0.f, As = 0.f;
#pragma unroll
    for (int i = 0; i < 20; ++i) {
        int jj = 3 * t0 + i + 80;
        if (jj >= NCH) jj -= NCH;
        if (jj >= NCH) jj -= NCH;
        float4 v = *(const float4*)(cwb + (size_t)jj * cstep);
        s0 += v.x; s1 += v.y; s2 += v.z; s3 += v.w;
        As += cab[(size_t)jj * KC];
    }
    const float4 cen = *(const float4*)&centers[(size_t)k * CD + c4];

#pragma unroll
    for (int t = t0; t < t0 + TW; ++t) {
        float r0 = s0 - cen.x * As;
        float r1 = s1 - cen.y * As;
        float r2 = s2 - cen.z * As;
        float r3 = s3 - cen.w * As;
        float ns = r0 * r0 + r1 * r1 + r2 * r2 + r3 * r3;
#pragma unroll
        for (int off = 16; off > 0; off >>= 1)
            ns += __shfl_xor_sync(0xffffffffu, ns, off);
        float inv = 0.125f / fmaxf(sqrtf(ns), 1e-12f);

        uint32_t h01, l01, h23, l23;
        bsplit2(r0 * inv, r1 * inv, h01, l01);
        bsplit2(r2 * inv, r3 * inv, h23, l23);
        size_t idx = (size_t)(n * NW + t) * KD + (size_t)k * CD + c4;
        *(uint2*)&g_vh[idx] = make_uint2(h01, h23);
        *(uint2*)&g_vl[idx] = make_uint2(l01, l23);

        if (t < t0 + TW - 1) {
#pragma unroll
            for (int d = 0; d < 3; ++d) {
                int ja = 3 * t + 10 + d;
                if (ja >= NCH) ja -= NCH;
                int js = 3 * t + 80 + d;
                if (js >= NCH) js -= NCH;
                if (js >= NCH) js -= NCH;
                float4 va = *(const float4*)(cwb + (size_t)ja * cstep);
                float4 vs = *(const float4*)(cwb + (size_t)js * cstep);
                s0 += va.x - vs.x; s1 += va.y - vs.y;
                s2 += va.z - vs.z; s3 += va.w - vs.w;
                As += cab[(size_t)ja * KC] - cab[(size_t)js * KC];
            }
        }
    }
}

// ---------------------------------------------------------------------------
// Kernel C2 (R7 measured-best config): BM=128, BN=64, K-chunk 256
// (4 stages of 64), grid (2,4,32), cp.async double-buffered.
// ---------------------------------------------------------------------------
#define C2_RS   72
#define C2_AH   0
#define C2_AL   18432
#define C2_BH   36864
#define C2_BL   46080
#define C2_BUF  55296
#define C2_SMEM (C2_BUF * 2)

__device__ __forceinline__ void c2_stage(uint32_t sbuf, int m0, int n0, int kb,
                                         int tid) {
#pragma unroll
    for (int it = 0; it < 4; ++it) {
        int p = tid + it * 256;
        int row = p >> 3, cg = (p & 7) * 8;
        size_t g = (size_t)(m0 + row) * KD + kb + cg;
        cpa16(sbuf + C2_AH + (row * C2_RS + cg) * 2, &g_vh[g]);
        cpa16(sbuf + C2_AL + (row * C2_RS + cg) * 2, &g_vl[g]);
    }
#pragma unroll
    for (int it = 0; it < 2; ++it) {
        int p = tid + it * 256;
        int row = p >> 3, cg = (p & 7) * 8;
        size_t g = (size_t)(n0 + row) * KD + kb + cg;
        cpa16(sbuf + C2_BH + (row * C2_RS + cg) * 2, &g_wh[g]);
        cpa16(sbuf + C2_BL + (row * C2_RS + cg) * 2, &g_wl[g]);
    }
}

__global__ __launch_bounds__(256, 1) void kC2() {
    extern __shared__ char smem[];
    const uint32_t sb = smem_u32(smem);
    const int tid = threadIdx.x;
    const int wid = tid >> 5;
    const int L   = tid & 31;
    const int m0  = blockIdx.x * 128;
    const int n0  = blockIdx.y * 64;
    const int k0  = blockIdx.z * 256;

    const int wm = wid & 1;
    const int wn = wid >> 1;

    float acc[4][2][4];
#pragma unroll
    for (int mi = 0; mi < 4; mi++)
#pragma unroll
        for (int ni = 0; ni < 2; ni++)
#pragma unroll
            for (int e = 0; e < 4; e++) acc[mi][ni][e] = 0.f;

    const int a_row = (L & 7) + ((L >> 3) & 1) * 8;
    const int a_ch  = (L >> 4) * 8;
    const int b_row = (L & 7) + (L >> 4) * 8;
    const int b_ch  = ((L >> 3) & 1) * 8;

    c2_stage(sb, m0, n0, k0, tid);
    CPA_COMMIT();

#pragma unroll
    for (int stage = 0; stage < 4; ++stage) {
        if (stage < 3) {
            c2_stage(sb + ((stage + 1) & 1) * C2_BUF, m0, n0, k0 + (stage + 1) * 64, tid);
            CPA_COMMIT();
            CPA_WAIT1();
        } else {
            CPA_WAIT0();
        }
        __syncthreads();
        uint32_t bufb = sb + (stage & 1) * C2_BUF;

#pragma unroll
        for (int ks = 0; ks < 4; ++ks) {
            int kc = ks * 16;
            uint32_t bhf[4], blf[4];
            {
                uint32_t off = (uint32_t)((wn * 16 + b_row) * C2_RS + kc + b_ch) * 2;
                ldm_x4(bhf, bufb + C2_BH + off);
                ldm_x4(blf, bufb + C2_BL + off);
            }
#pragma unroll
            for (int mi = 0; mi < 4; mi++) {
                uint32_t ah[4], al[4];
                uint32_t off = (uint32_t)((wm * 64 + mi * 16 + a_row) * C2_RS + kc + a_ch) * 2;
                ldm_x4(ah, bufb + C2_AH + off);
                ldm_x4(al, bufb + C2_AL + off);
#pragma unroll
                for (int ni = 0; ni < 2; ni++) {
                    mma16816(acc[mi][ni], ah, bhf[ni * 2], bhf[ni * 2 + 1]);
                    mma16816(acc[mi][ni], ah, blf[ni * 2], blf[ni * 2 + 1]);
                    mma16816(acc[mi][ni], al, bhf[ni * 2], bhf[ni * 2 + 1]);
                }
            }
        }
        __syncthreads();
    }

    float* pb = g_part + (size_t)blockIdx.z * NR * OD;
#pragma unroll
    for (int mi = 0; mi < 4; mi++) {
        int m_lo = m0 + wm * 64 + mi * 16 + (L >> 2);
        int nn   = n0 + wn * 16 + (L & 3) * 2;
#pragma unroll
        for (int ni = 0; ni < 2; ni++) {
            int nc = nn + ni * 8;
            if (m_lo < NR)
                *(float2*)&pb[(size_t)m_lo * OD + nc] =
                    make_float2(acc[mi][ni][0], acc[mi][ni][1]);
            if (m_lo + 8 < NR)
                *(float2*)&pb[(size_t)(m_lo + 8) * OD + nc] =
                    make_float2(acc[mi][ni][2], acc[mi][ni][3]);
        }
    }
}

__global__ __launch_bounds__(256) void kC3(const float* __restrict__ mb,
                                           float* __restrict__ out) {
    __shared__ float red[8];
    const int rrow = blockIdx.x;
    const int tid  = threadIdx.x;
    float s = mb[tid];
#pragma unroll
    for (int ks = 0; ks < KSP; ks++)
        s += g_part[((size_t)ks * NR + rrow) * OD + tid];
    float sq = s * s;
#pragma unroll
    for (int off = 16; off > 0; off >>= 1)
        sq += __shfl_xor_sync(0xffffffffu, sq, off);
    if ((tid & 31) == 0) red[tid >> 5] = sq;
    __syncthreads();
    float tot = 0.f;
#pragma unroll
    for (int i = 0; i < 8; i++) tot += red[i];
    out[(size_t)rrow * OD + tid] = s / fmaxf(sqrtf(tot), 1e-12f);
}

extern "C" void kernel_launch(void* const* d_in, const int* in_sizes, int n_in,
                              void* d_out, int out_size) {
    (void)in_sizes; (void)n_in; (void)out_size;
    const float* x       = (const float*)d_in[0];
    const float* centers = (const float*)d_in[1];
    const float* cw      = (const float*)d_in[2];
    const float* cb      = (const float*)d_in[3];
    const float* mw      = (const float*)d_in[4];
    const float* mb      = (const float*)d_in[5];
    float* out = (float*)d_out;

    static cudaStream_t s2 = nullptr;
    static cudaEvent_t evFork = nullptr, evJoin = nullptr;
    if (!s2) {
        cudaStreamCreateWithFlags(&s2, cudaStreamNonBlocking);
        cudaEventCreateWithFlags(&evFork, cudaEventDisableTiming);
        cudaEventCreateWithFlags(&evJoin, cudaEventDisableTiming);
        cudaFuncSetAttribute(kF, cudaFuncAttributeMaxDynamicSharedMemorySize, F_SMEM);
        cudaFuncSetAttribute(kC2, cudaFuncAttributeMaxDynamicSharedMemorySize, C2_SMEM);
    }

    kWc<<<KC * CD / (256 * 4), 256>>>(cw);

    cudaEventRecord(evFork, 0);
    cudaStreamWaitEvent(s2, evFork, 0);
    kW<<<OD * KD / (256 * 8), 256, 0, s2>>>(mw);
    cudaEventRecord(evJoin, s2);

    kF<<<NB * NCH, 320, F_SMEM>>>(x, cb);
    kC1<<<NB * KC * TG / 8, 256>>>(centers);
    cudaStreamWaitEvent(0, evJoin, 0);
    kC2<<<dim3(2, 4, KSP), 256, C2_SMEM>>>();
    kC3<<<NR, 256>>>(mb, out);
}